// round 17
// baseline (speedup 1.0000x reference)
#include <cuda_runtime.h>
#include <cuda_bf16.h>
#include <cstdint>

#define D  512
#define DD (D * D)

#if !defined(__CUDA_ARCH__) || defined(__CUDA_ARCH_FEAT_SM103_ALL) || defined(__CUDA_ARCH_FEAT_SM100_ALL)
#define HAS_TCGEN05 1
#endif

// fp32 intermediate ping-pong buffers
__device__ float g_buf0[500 * DD];
__device__ float g_buf1[250 * DD];

// ---------------- PTX helpers ----------------
__device__ __forceinline__ uint32_t smem_u32(const void* p) {
    uint32_t a;
    asm("{ .reg .u64 t; cvta.to.shared.u64 t, %1; cvt.u32.u64 %0, t; }" : "=r"(a) : "l"(p));
    return a;
}
__device__ __forceinline__ uint32_t elect_one() {
    uint32_t p;
    asm volatile("{ .reg .pred p; elect.sync _|p, 0xFFFFFFFF; selp.b32 %0,1,0,p; }" : "=r"(p));
    return p;
}
__device__ __forceinline__ void mbar_wait(uint32_t addr, uint32_t parity) {
    asm volatile(
        "{\n\t.reg .pred P;\n\t"
        "WL_%=:\n\t"
        "mbarrier.try_wait.parity.acquire.cta.shared::cta.b64 P, [%0], %1, 0x989680;\n\t"
        "@!P bra WL_%=;\n\t}"
        :: "r"(addr), "r"(parity) : "memory");
}
__device__ __forceinline__ uint64_t desc_k(uint32_t addr) {
    return ((uint64_t)2 << 61) | ((uint64_t)1 << 46) | ((uint64_t)64 << 32) |
           ((uint64_t)1 << 16) | ((addr >> 4) & 0x3FFF);
}
// idesc: f32 accum, bf16 A/B, N=128, M=128 (same encoding as validated SS use;
// operand form TS is expressed in instruction syntax, not idesc)
#define IDESC 0x8200490u

#ifdef HAS_TCGEN05
// TS-form MMA: A in TMEM (validated pattern: test_mma_iter.cu)
__device__ __forceinline__ void mma_ts(uint32_t d, uint32_t a, uint64_t b, uint32_t en) {
    asm volatile(
        "{\n\t.reg .pred p;\n\tsetp.ne.u32 p, %4, 0;\n\t"
        "tcgen05.mma.cta_group::1.kind::f16 [%0], [%1], %2, %3, {%5,%5,%5,%5}, p;\n\t}"
        :: "r"(d), "r"(a), "l"(b), "r"(IDESC), "r"(en), "r"(0u) : "memory");
}
__device__ __forceinline__ void sttm_x8(uint32_t addr, const uint32_t* r) {
    asm volatile(
        "tcgen05.st.sync.aligned.32x32b.x8.b32 [%0], {%1,%2,%3,%4,%5,%6,%7,%8};"
        :: "r"(addr), "r"(r[0]), "r"(r[1]), "r"(r[2]), "r"(r[3]),
           "r"(r[4]), "r"(r[5]), "r"(r[6]), "r"(r[7]) : "memory");
}
#define LDTM_X32(r, addr)                                                        \
    asm volatile(                                                                \
        "tcgen05.ld.sync.aligned.32x32b.x32.b32 "                                \
        "{%0,%1,%2,%3,%4,%5,%6,%7,%8,%9,%10,%11,%12,%13,%14,%15,"                \
        "%16,%17,%18,%19,%20,%21,%22,%23,%24,%25,%26,%27,%28,%29,%30,%31},[%32];"\
        : "=r"((r)[0]), "=r"((r)[1]), "=r"((r)[2]), "=r"((r)[3]),                \
          "=r"((r)[4]), "=r"((r)[5]), "=r"((r)[6]), "=r"((r)[7]),                \
          "=r"((r)[8]), "=r"((r)[9]), "=r"((r)[10]), "=r"((r)[11]),              \
          "=r"((r)[12]), "=r"((r)[13]), "=r"((r)[14]), "=r"((r)[15]),            \
          "=r"((r)[16]), "=r"((r)[17]), "=r"((r)[18]), "=r"((r)[19]),            \
          "=r"((r)[20]), "=r"((r)[21]), "=r"((r)[22]), "=r"((r)[23]),            \
          "=r"((r)[24]), "=r"((r)[25]), "=r"((r)[26]), "=r"((r)[27]),            \
          "=r"((r)[28]), "=r"((r)[29]), "=r"((r)[30]), "=r"((r)[31])             \
        : "r"(addr))
#endif

__device__ __forceinline__ uint32_t pack_bf2(float a, float b) {
    uint32_t r;
    asm("cvt.rn.bf16x2.f32 %0, %1, %2;" : "=r"(r) : "f"(b), "f"(a));
    return r;
}
__device__ __forceinline__ void split_pair(float a, float b, uint32_t& h, uint32_t& l) {
    h = pack_bf2(a, b);
    float ha = __uint_as_float(h << 16);
    float hb = __uint_as_float(h & 0xffff0000u);
    l = pack_bf2(a - ha, b - hb);
}

// TMEM map: alloc 256 cols. D @0 (128 fp32 cols), AH @128 (32), AL @160 (32).
#define TM_D  0u
#define TM_AH 128u
#define TM_AL 160u

// smem: header 1KB, BH 16KB, BL 16KB; epilogue ws reuses [1024, 34816)
#define SM_TMEMP 0
#define SM_MBAR  8
#define SM_BH    1024
#define SM_BL    (SM_BH + 16384)
#define SM_REST  (1024 + 33792)          // 34816 (covers ws 8*4224)
#define SM_SCR   SM_REST                 // FIRST: fp32 scratch 64x128 = 32KB
#define SM_FIRST (SM_SCR + 32768)        // 67584

// C_p = M[2p+1] @ M[2p], 512x512 fp32.
// Warp specialization: warps 0-3 = L path (row-per-thread -> split -> STTM to
// TMEM); warps 4-7 = B path (coalesced LDG -> split -> swizzled STS planes).
// MMA is TS-form (A from TMEM, B from SMEM), halving smem-crossbar traffic.
// Role scheme / pipeline / epilogue identical to R14 (validated).
template <bool FIRST>
__global__ void __launch_bounds__(256) tree_gemm(const float* __restrict__ in,
                                                 float* __restrict__ out,
                                                 int force_normal)
{
#ifndef HAS_TCGEN05
    __trap();
#else
    extern __shared__ char smem[];
    const uint32_t sb = smem_u32(smem);
    const int tid = threadIdx.x;
    const int wid = tid >> 5, lid = tid & 31;
    const int p = blockIdx.z;
    const float* __restrict__ L = in + (size_t)(2 * p + 1) * DD;
    const float* __restrict__ R = in + (size_t)(2 * p) * DD;
    float* __restrict__ C = out + (size_t)p * DD;
    const int bm = blockIdx.y * 128, bn = blockIdx.x * 128;
    const bool storeT = ((p & 1) == 0) && !force_normal;

    if (wid == 0) {
        asm volatile("tcgen05.alloc.cta_group::1.sync.aligned.shared::cta.b32 [%0], %1;"
                     :: "r"(sb + SM_TMEMP), "r"(256u) : "memory");
        asm volatile("tcgen05.relinquish_alloc_permit.cta_group::1.sync.aligned;");
    }
    if (tid == 0)
        asm volatile("mbarrier.init.shared.b64 [%0], %1;" :: "r"(sb + SM_MBAR), "r"(1u) : "memory");
    __syncthreads();
    uint32_t tmem;
    asm volatile("ld.shared.b32 %0,[%1];" : "=r"(tmem) : "r"(sb + SM_TMEMP));

    const bool lSide = tid < 128;
    const uint32_t warp_off = (uint32_t)(tid >> 5) << 21;   // L-side only (tid<128)
    // B-side (non-FIRST): t in 0..127, rows brow0+8i, k cols bk4..bk4+3
    const int t    = tid & 127;
    const int brow0 = t >> 4;           // 0..7
    const int bk4   = (t & 15) * 4;     // 0..60
    // FIRST R-staging: k-rows kr0+4i, n cols rn4
    const int kr0 = t >> 5;             // 0..3
    const int rn4 = (t & 31) * 4;       // 0..124
    const int cn  = t;                  // FIRST column phase

    float4 reg[16];
    // preload chunk 0
    if (lSide) {
        const float* Lp = L + (size_t)(bm + tid) * D;
        #pragma unroll
        for (int j = 0; j < 16; j++) reg[j] = *(const float4*)(Lp + j * 4);
    } else if (FIRST) {
        #pragma unroll
        for (int i = 0; i < 16; i++)
            reg[i] = *(const float4*)(R + (size_t)(kr0 + 4 * i) * D + bn + rn4);
    } else {
        const float* Bp = R + (size_t)(bn + brow0) * D + bk4;
        #pragma unroll
        for (int i = 0; i < 16; i++)
            reg[i] = *(const float4*)(Bp + (size_t)8 * i * D);
    }

    for (int c = 0; c < 8; c++) {
        if (FIRST && !lSide) {
            // stage R chunk (transform applied) into fp32 scratch
            #pragma unroll
            for (int i = 0; i < 16; i++) {
                float4 v = reg[i];
                const int kk = kr0 + 4 * i;
                const int gr = c * 64 + kk, gc = bn + rn4;
                v.x = fmaf(v.x, -1e-3f, (gr == gc + 0) ? 1.f : 0.f);
                v.y = fmaf(v.y, -1e-3f, (gr == gc + 1) ? 1.f : 0.f);
                v.z = fmaf(v.z, -1e-3f, (gr == gc + 2) ? 1.f : 0.f);
                v.w = fmaf(v.w, -1e-3f, (gr == gc + 3) ? 1.f : 0.f);
                *(float4*)(smem + SM_SCR + (size_t)kk * 512 + (size_t)rn4 * 4) = v;
            }
        }

        if (c > 0) mbar_wait(sb + SM_MBAR, (uint32_t)((c - 1) & 1));

        if (lSide) {
            // L: (transform) + split -> STTM AH/AL, 4 rounds of 8 cols
            #pragma unroll
            for (int r = 0; r < 4; r++) {
                uint32_t ah[8], al[8];
                #pragma unroll
                for (int j = 0; j < 4; j++) {
                    float4 v = reg[4 * r + j];
                    if (FIRST) {
                        const int gr = bm + tid, gc = c * 64 + r * 16 + j * 4;
                        v.x = fmaf(v.x, -1e-3f, (gr == gc + 0) ? 1.f : 0.f);
                        v.y = fmaf(v.y, -1e-3f, (gr == gc + 1) ? 1.f : 0.f);
                        v.z = fmaf(v.z, -1e-3f, (gr == gc + 2) ? 1.f : 0.f);
                        v.w = fmaf(v.w, -1e-3f, (gr == gc + 3) ? 1.f : 0.f);
                    }
                    split_pair(v.x, v.y, ah[2 * j],     al[2 * j]);
                    split_pair(v.z, v.w, ah[2 * j + 1], al[2 * j + 1]);
                }
                sttm_x8(tmem + TM_AH + r * 8 + warp_off, ah);
                sttm_x8(tmem + TM_AL + r * 8 + warp_off, al);
            }
            asm volatile("tcgen05.wait::st.sync.aligned;" ::: "memory");
        } else if (!FIRST) {
            // B: split -> swizzled STS planes (R14's store pattern)
            #pragma unroll
            for (int i = 0; i < 16; i++) {
                float4 v = reg[i];
                const int n = brow0 + 8 * i;
                uint32_t h0, l0, h1, l1;
                split_pair(v.x, v.y, h0, l0);
                split_pair(v.z, v.w, h1, l1);
                uint32_t off = (uint32_t)(n * 128 + bk4 * 2);
                off ^= (off >> 3) & 0x70;
                *(uint2*)(smem + SM_BH + off) = make_uint2(h0, h1);
                *(uint2*)(smem + SM_BL + off) = make_uint2(l0, l1);
            }
        }
        __syncthreads();

        if (FIRST) {
            if (!lSide) {
                // column phase: transpose scratch -> B planes
                const float* scr = (const float*)(smem + SM_SCR);
                const uint32_t swx = (uint32_t)((cn & 7) << 4);
                #pragma unroll
                for (int j = 0; j < 8; j++) {
                    float f[8];
                    #pragma unroll
                    for (int q = 0; q < 8; q++) f[q] = scr[(8 * j + q) * 128 + cn];
                    uint32_t h[4], l[4];
                    #pragma unroll
                    for (int q = 0; q < 4; q++)
                        split_pair(f[2 * q], f[2 * q + 1], h[q], l[q]);
                    const uint32_t off = (uint32_t)(cn * 128) + (((uint32_t)(j * 16)) ^ swx);
                    *(uint4*)(smem + SM_BH + off) = make_uint4(h[0], h[1], h[2], h[3]);
                    *(uint4*)(smem + SM_BL + off) = make_uint4(l[0], l[1], l[2], l[3]);
                }
            }
            __syncthreads();
        }

        if (wid == 0) {
            asm volatile("fence.proxy.async.shared::cta;" ::: "memory");
            if (elect_one()) {
                const uint64_t bh = desc_k(sb + SM_BH);
                const uint64_t bl = desc_k(sb + SM_BL);
                #pragma unroll
                for (int ks = 0; ks < 4; ks++)
                    mma_ts(tmem + TM_D, tmem + TM_AH + ks * 8, bh + ks * 2,
                           (c == 0 && ks == 0) ? 0u : 1u);
                #pragma unroll
                for (int ks = 0; ks < 4; ks++)
                    mma_ts(tmem + TM_D, tmem + TM_AH + ks * 8, bl + ks * 2, 1u);
                #pragma unroll
                for (int ks = 0; ks < 4; ks++)
                    mma_ts(tmem + TM_D, tmem + TM_AL + ks * 8, bh + ks * 2, 1u);
                asm volatile(
                    "tcgen05.commit.cta_group::1.mbarrier::arrive::one.shared::cluster.b64 [%0];"
                    :: "r"(sb + SM_MBAR) : "memory");
            }
        }

        // prefetch next chunk (overlaps MMA)
        if (c < 7) {
            if (lSide) {
                const float* Lp = L + (size_t)(bm + tid) * D + (c + 1) * 64;
                #pragma unroll
                for (int j = 0; j < 16; j++) reg[j] = *(const float4*)(Lp + j * 4);
            } else if (FIRST) {
                #pragma unroll
                for (int i = 0; i < 16; i++)
                    reg[i] = *(const float4*)(R + (size_t)((c + 1) * 64 + kr0 + 4 * i) * D + bn + rn4);
            } else {
                const float* Bp = R + (size_t)(bn + brow0) * D + (c + 1) * 64 + bk4;
                #pragma unroll
                for (int i = 0; i < 16; i++)
                    reg[i] = *(const float4*)(Bp + (size_t)8 * i * D);
            }
        }
    }
    mbar_wait(sb + SM_MBAR, 1u);  // completion 7 (in-loop waits consumed 0-6)
    asm volatile("tcgen05.fence::after_thread_sync;" ::: "memory");

    // epilogue (R14 exact): normal or transposed store
    {
        uint32_t r0[32], r1[32];
        const int ch = (wid >= 4) ? 64 : 0;
        const int m0 = (wid & 3) * 32;
        LDTM_X32(r0, tmem + TM_D + (uint32_t)ch);
        LDTM_X32(r1, tmem + TM_D + (uint32_t)ch + 32);
        asm volatile("tcgen05.wait::ld.sync.aligned;" ::: "memory");

        if (!storeT) {
            const int row = bm + m0 + lid;
            float* cp = C + (size_t)row * D + bn + ch;
            #pragma unroll
            for (int j = 0; j < 32; j += 4)
                *(float4*)(cp + j) = make_float4(
                    __uint_as_float(r0[j]), __uint_as_float(r0[j + 1]),
                    __uint_as_float(r0[j + 2]), __uint_as_float(r0[j + 3]));
            #pragma unroll
            for (int j = 0; j < 32; j += 4)
                *(float4*)(cp + 32 + j) = make_float4(
                    __uint_as_float(r1[j]), __uint_as_float(r1[j + 1]),
                    __uint_as_float(r1[j + 2]), __uint_as_float(r1[j + 3]));
        } else {
            float* ws = (float*)(smem + 1024 + wid * (32 * 33 * 4));
            #pragma unroll
            for (int pass = 0; pass < 2; pass++) {
                const uint32_t* rr = pass ? r1 : r0;
                #pragma unroll
                for (int cc = 0; cc < 32; cc++)
                    ws[cc * 33 + lid] = __uint_as_float(rr[cc]);
                __syncwarp();
                float* gp = C + (size_t)(bn + ch + pass * 32 + lid) * D + bm + m0;
                #pragma unroll
                for (int r = 0; r < 32; r += 4) {
                    float4 v = make_float4(ws[lid * 33 + r],     ws[lid * 33 + r + 1],
                                           ws[lid * 33 + r + 2], ws[lid * 33 + r + 3]);
                    *(float4*)(gp + r) = v;
                }
                __syncwarp();
            }
        }
    }
    __syncthreads();
    if (wid == 0)
        asm volatile("tcgen05.dealloc.cta_group::1.sync.aligned.b32 %0, %1;"
                     :: "r"(tmem), "r"(256u));
#endif  // HAS_TCGEN05
}

// out = in^T  (512x512 fp32) — validated
__global__ void transpose512(const float* __restrict__ in, float* __restrict__ out)
{
    __shared__ float tb[32][33];
    const int bx = blockIdx.x * 32, by = blockIdx.y * 32;
    const int x = threadIdx.x, y0 = threadIdx.y;
    #pragma unroll
    for (int dy = 0; dy < 32; dy += 8)
        tb[y0 + dy][x] = in[(size_t)(by + y0 + dy) * D + bx + x];
    __syncthreads();
    #pragma unroll
    for (int dy = 0; dy < 32; dy += 8)
        out[(size_t)(bx + y0 + dy) * D + by + x] = tb[x][y0 + dy];
}

extern "C" void kernel_launch(void* const* d_in, const int* in_sizes, int n_in,
                              void* d_out, int out_size)
{
    (void)in_sizes; (void)n_in; (void)out_size;
    const float* A = (const float*)d_in[0];
    float* out = (float*)d_out;

    float *b0 = nullptr, *b1 = nullptr;
    cudaGetSymbolAddress((void**)&b0, g_buf0);
    cudaGetSymbolAddress((void**)&b1, g_buf1);

    cudaFuncSetAttribute((const void*)tree_gemm<true>,
                         cudaFuncAttributeMaxDynamicSharedMemorySize, SM_FIRST);
    cudaFuncSetAttribute((const void*)tree_gemm<false>,
                         cudaFuncAttributeMaxDynamicSharedMemorySize, SM_REST);

    // Level 1: 1000 raw A -> 500 products; outputs stored T (p even) / N (p odd)
    tree_gemm<true><<<dim3(4, 4, 500), 256, SM_FIRST>>>(A, b0, 0);

    int cnt = 500;
    float* src = b0;
    float* dst = b1;
    while (cnt > 1) {
        const int pairs = cnt >> 1;
        float* o = (cnt == 2) ? out : dst;
        tree_gemm<false><<<dim3(4, 4, pairs), 256, SM_REST>>>(src, o, (cnt == 2) ? 1 : 0);
        if (cnt & 1) {
            const float* lv = src + (size_t)(cnt - 1) * DD;
            float* ov = o + (size_t)pairs * DD;
            if (pairs & 1)
                transpose512<<<dim3(16, 16), dim3(32, 8)>>>(lv, ov);
            else
                cudaMemcpyAsync(ov, lv, DD * sizeof(float), cudaMemcpyDeviceToDevice);
        }
        cnt = pairs + (cnt & 1);
        float* t = src; src = dst; dst = t;
    }
}